// round 2
// baseline (speedup 1.0000x reference)
#include <cuda_runtime.h>
#include <math.h>

#define BB 64      // batch
#define SS 64      // seq / timesteps
#define IN 512     // input dim
#define HH 512     // hidden dim
#define G4 2048    // 4*H
#define NBLK 128   // persistent blocks for phase 2 (<=148 SMs, 1 CTA/SM -> all resident)

// ---------------- scratch (device globals; no allocation APIs) ----------------
__device__ float g_Gx[(size_t)SS * G4 * BB];   // [s][j][b], 33.5 MB
__device__ float g_h[2][BB * HH];              // double-buffered hidden state
__device__ unsigned int g_bar_cnt = 0;
__device__ volatile unsigned int g_bar_gen = 0;

// ---------------- grid-wide barrier (all NBLK blocks resident) ----------------
__device__ __forceinline__ void grid_sync_all() {
    __syncthreads();
    if (threadIdx.x == 0) {
        unsigned int gen = g_bar_gen;
        __threadfence();
        if (atomicAdd(&g_bar_cnt, 1u) == NBLK - 1) {
            g_bar_cnt = 0;
            __threadfence();
            g_bar_gen = gen + 1;
        } else {
            while (g_bar_gen == gen) { __nanosleep(64); }
        }
        __threadfence();
    }
    __syncthreads();
}

// =====================================================================
// Phase 1: Gx[s][j][b] = sum_k x[b][s][k] * W_ih[s][j][k]
// grid (32 j-tiles, 64 s), 256 threads, 64x64 tile, Ktile=32, 4x4 microtile
// =====================================================================
__global__ __launch_bounds__(256) void gemm_x_kernel(
    const float* __restrict__ x, const float* __restrict__ Wih) {
    __shared__ float As[32][64];   // [k][b]
    __shared__ float Bs[32][64];   // [k][j]

    const int s   = blockIdx.y;
    const int j0  = blockIdx.x * 64;
    const int tid = threadIdx.x;
    const int ty  = tid >> 4;   // b-group 0..15
    const int tx  = tid & 15;   // j-group 0..15

    const float* xA = x + (size_t)s * IN;                      // + b*(SS*IN) per row
    const float* wB = Wih + ((size_t)s * G4 + j0) * IN;        // rows j, stride IN

    float acc[4][4];
#pragma unroll
    for (int i = 0; i < 4; i++)
#pragma unroll
        for (int j = 0; j < 4; j++) acc[i][j] = 0.f;

    for (int k0 = 0; k0 < IN; k0 += 32) {
#pragma unroll
        for (int p = 0; p < 2; p++) {
            int fi = tid * 2 + p;          // 0..511 float4 index
            int r  = fi >> 3;              // row 0..63
            int kk = (fi & 7) << 2;        // k within chunk
            float4 va = *(const float4*)(xA + (size_t)r * (SS * IN) + k0 + kk);
            As[kk + 0][r] = va.x; As[kk + 1][r] = va.y;
            As[kk + 2][r] = va.z; As[kk + 3][r] = va.w;
            float4 vb = *(const float4*)(wB + (size_t)r * IN + k0 + kk);
            Bs[kk + 0][r] = vb.x; Bs[kk + 1][r] = vb.y;
            Bs[kk + 2][r] = vb.z; Bs[kk + 3][r] = vb.w;
        }
        __syncthreads();
#pragma unroll
        for (int k = 0; k < 32; k++) {
            float4 av = *(const float4*)&As[k][ty << 2];
            float4 bv = *(const float4*)&Bs[k][tx << 2];
            float a[4] = {av.x, av.y, av.z, av.w};
            float b[4] = {bv.x, bv.y, bv.z, bv.w};
#pragma unroll
            for (int i = 0; i < 4; i++)
#pragma unroll
                for (int j = 0; j < 4; j++)
                    acc[i][j] = fmaf(a[i], b[j], acc[i][j]);
        }
        __syncthreads();
    }

    float* og = g_Gx + ((size_t)s * G4 + j0) * BB;
#pragma unroll
    for (int j = 0; j < 4; j++) {
        float4 v = make_float4(acc[0][j], acc[1][j], acc[2][j], acc[3][j]);
        *(float4*)&og[(size_t)(tx * 4 + j) * BB + (ty << 2)] = v;
    }
}

// =====================================================================
// Phase 2: persistent recurrence. 128 blocks x 256 threads.
// Block owns 4 h-columns (jh0 = blockIdx.x*4). Thread (b, jhl) owns c[b][jh]
// in a register and computes all 4 gates for its cell each step.
// h_prev staged in smem (padded rows, conflict-free float4), W_hh rows in smem.
// =====================================================================
#define HPAD 516                        // 512 + 4 pad -> conflict-free float4 rows
#define SH_H_FLOATS (BB * HPAD)         // 33024
#define SH_W_FLOATS (16 * HH)           // 8192
#define SH_ST_FLOATS (BB * 4)           // 256
#define SMEM2_BYTES ((SH_H_FLOATS + SH_W_FLOATS + SH_ST_FLOATS) * 4)  // 165888

__global__ __launch_bounds__(256, 1) void lstm_rec_kernel(
    const float* __restrict__ Whh, float* __restrict__ out) {
    extern __shared__ float smem[];
    float* sh_h  = smem;                              // [64][HPAD]
    float* sh_W  = smem + SH_H_FLOATS;                // [16][512] rows: gate*4+jhl
    float* sh_st = sh_W + SH_W_FLOATS;                // [64][4] h staging

    const int tid = threadIdx.x;
    const int b   = tid & 63;
    const int jhl = tid >> 6;                         // 0..3
    const int jh0 = blockIdx.x * 4;
    const int jh  = jh0 + jhl;

    float c = 0.f;
    g_h[0][b * HH + jh] = 0.f;                        // zero initial h (block's slice)
    grid_sync_all();

    for (int s = 0; s < SS; s++) {
        const int cur = s & 1, nxt = cur ^ 1;

        // stage h_prev -> smem (8192 float4, 32 per thread, coalesced)
        const float* hsrc = g_h[cur];
#pragma unroll
        for (int p = 0; p < 32; p++) {
            int fi = p * 256 + tid;                   // 0..8191
            int hb = fi >> 7;                         // row (128 float4/row)
            int hk = (fi & 127) << 2;
            float4 v = *(const float4*)(hsrc + hb * HH + hk);
            *(float4*)&sh_h[hb * HPAD + hk] = v;
        }
        // stage 16 W_hh rows -> smem (2048 float4, 8 per thread)
        const float* wsrc = Whh + (size_t)s * G4 * HH;
#pragma unroll
        for (int p = 0; p < 8; p++) {
            int fi = p * 256 + tid;                   // 0..2047
            int r  = fi >> 7;                         // local row 0..15
            int kk = (fi & 127) << 2;
            int gate = r >> 2, jl = r & 3;
            float4 v = *(const float4*)(wsrc + (size_t)(gate * HH + jh0 + jl) * HH + kk);
            *(float4*)&sh_W[r * HH + kk] = v;
        }
        __syncthreads();

        // gates start from precomputed Gx (coalesced: b contiguous)
        const float* gx = g_Gx + (size_t)s * G4 * BB;
        float a0 = gx[(size_t)(0 * HH + jh) * BB + b];
        float a1 = gx[(size_t)(1 * HH + jh) * BB + b];
        float a2 = gx[(size_t)(2 * HH + jh) * BB + b];
        float a3 = gx[(size_t)(3 * HH + jh) * BB + b];

        const float* hrow = &sh_h[b * HPAD];
        const float* w0 = &sh_W[(0 * 4 + jhl) * HH];
        const float* w1 = &sh_W[(1 * 4 + jhl) * HH];
        const float* w2 = &sh_W[(2 * 4 + jhl) * HH];
        const float* w3 = &sh_W[(3 * 4 + jhl) * HH];

#pragma unroll 4
        for (int k = 0; k < HH; k += 4) {
            float4 hv = *(const float4*)(hrow + k);
            float4 v0 = *(const float4*)(w0 + k);
            float4 v1 = *(const float4*)(w1 + k);
            float4 v2 = *(const float4*)(w2 + k);
            float4 v3 = *(const float4*)(w3 + k);
            a0 = fmaf(hv.x, v0.x, a0); a0 = fmaf(hv.y, v0.y, a0);
            a0 = fmaf(hv.z, v0.z, a0); a0 = fmaf(hv.w, v0.w, a0);
            a1 = fmaf(hv.x, v1.x, a1); a1 = fmaf(hv.y, v1.y, a1);
            a1 = fmaf(hv.z, v1.z, a1); a1 = fmaf(hv.w, v1.w, a1);
            a2 = fmaf(hv.x, v2.x, a2); a2 = fmaf(hv.y, v2.y, a2);
            a2 = fmaf(hv.z, v2.z, a2); a2 = fmaf(hv.w, v2.w, a2);
            a3 = fmaf(hv.x, v3.x, a3); a3 = fmaf(hv.y, v3.y, a3);
            a3 = fmaf(hv.z, v3.z, a3); a3 = fmaf(hv.w, v3.w, a3);
        }

        float ig = 1.f / (1.f + __expf(-a0));
        float fg = 1.f / (1.f + __expf(-a1));
        float gg = tanhf(a2);
        float og = 1.f / (1.f + __expf(-a3));
        c = fg * c + ig * gg;
        float hval = og * tanhf(c);

        __syncthreads();                 // protect sh_st reuse
        sh_st[b * 4 + jhl] = hval;
        __syncthreads();
        if (tid < 64) {                  // one float4 per batch row
            float4 hv4 = *(float4*)&sh_st[tid * 4];
            *(float4*)&g_h[nxt][tid * HH + jh0] = hv4;
            *(float4*)&out[((size_t)tid * SS + s) * HH + jh0] = hv4;
        }
        grid_sync_all();                 // publish h before next step reads it
    }
}

// ---------------------------------------------------------------------
extern "C" void kernel_launch(void* const* d_in, const int* in_sizes, int n_in,
                              void* d_out, int out_size) {
    const float* x   = (const float*)d_in[0];
    const float* Wih = (const float*)d_in[1];
    const float* Whh = (const float*)d_in[2];
    float* out = (float*)d_out;

    dim3 g1(32, 64);   // 32 j-tiles of 64, 64 timesteps
    gemm_x_kernel<<<g1, 256>>>(x, Wih);

    cudaFuncSetAttribute(lstm_rec_kernel,
                         cudaFuncAttributeMaxDynamicSharedMemorySize, SMEM2_BYTES);
    lstm_rec_kernel<<<NBLK, 256, SMEM2_BYTES>>>(Whh, out);
}